// round 1
// baseline (speedup 1.0000x reference)
#include <cuda_runtime.h>
#include <cstddef>

#define Bn  64
#define Tn  512
#define DIn 512
#define Hn  1024
#define G4n 4096

// Scratch for the precomputed input projection: (B, T, 4H) fp32 = 512 MB.
__device__ float g_xproj[(size_t)Bn * Tn * G4n];

// ---------------- packed f32x2 helpers (exact fp32, 2x FFMA throughput) ----
__device__ __forceinline__ unsigned long long pack2(float lo, float hi) {
    unsigned long long r;
    asm("mov.b64 %0, {%1, %2};" : "=l"(r) : "f"(lo), "f"(hi));
    return r;
}
__device__ __forceinline__ void fma2(unsigned long long& d, unsigned long long a,
                                     unsigned long long b) {
    asm("fma.rn.f32x2 %0, %1, %2, %0;" : "+l"(d) : "l"(a), "l"(b));
}
__device__ __forceinline__ float2 unpack2(unsigned long long v) {
    float lo, hi;
    asm("mov.b64 {%0, %1}, %2;" : "=f"(lo), "=f"(hi) : "l"(v));
    return make_float2(lo, hi);
}

__device__ __forceinline__ float sigf(float x) {
    return 1.0f / (1.0f + __expf(-x));
}

// ============================================================================
// Kernel 1: x_proj[m, n] = sum_k inputs[m, k] * W_ih[n, k] + (b_ih[n]+b_hh[n])
//   M = B*T = 32768, N = 4H = 4096, K = DI = 512
//   Tile 64x64x32, 256 threads, per-thread 4x4 via f32x2 row pairs.
// ============================================================================
__global__ __launch_bounds__(256) void xproj_kernel(
    const float* __restrict__ A,      // (M, K) = inputs flattened
    const float* __restrict__ Wih,    // (N, K)
    const float* __restrict__ bih,
    const float* __restrict__ bhh)
{
    __shared__ float sA[32][66];   // transposed: sA[kk][m], pad 66 for 2-way-max banks + 8B align
    __shared__ float sB[32][66];   // transposed: sB[kk][n]

    const int tid = threadIdx.x;
    const int tx  = tid & 15;      // 16 col groups (4 cols each)
    const int ty  = tid >> 4;      // 16 row groups (4 rows each)
    const int n0  = blockIdx.x * 64;
    const int m0  = blockIdx.y * 64;

    unsigned long long acc[2][4];
#pragma unroll
    for (int p = 0; p < 2; ++p)
#pragma unroll
        for (int c = 0; c < 4; ++c) acc[p][c] = 0ULL;

    for (int k0 = 0; k0 < DIn; k0 += 32) {
        // Fill: 512 float4 per tile per matrix; lanes q-fast -> coalesced LDG.128,
        // STS transposed scatter is 2-way conflicted (stride 66).
#pragma unroll
        for (int nIt = 0; nIt < 2; ++nIt) {
            int i = tid + nIt * 256;
            int q = i & 7;            // 4-kk chunk
            int r = i >> 3;           // row/col within tile
            float4 va = *(const float4*)&A[(size_t)(m0 + r) * DIn + k0 + 4 * q];
            sA[4 * q + 0][r] = va.x; sA[4 * q + 1][r] = va.y;
            sA[4 * q + 2][r] = va.z; sA[4 * q + 3][r] = va.w;
            float4 vb = *(const float4*)&Wih[(size_t)(n0 + r) * DIn + k0 + 4 * q];
            sB[4 * q + 0][r] = vb.x; sB[4 * q + 1][r] = vb.y;
            sB[4 * q + 2][r] = vb.z; sB[4 * q + 3][r] = vb.w;
        }
        __syncthreads();

#pragma unroll
        for (int kk = 0; kk < 32; ++kk) {
            unsigned long long a0 = *(const unsigned long long*)&sA[kk][4 * ty];
            unsigned long long a1 = *(const unsigned long long*)&sA[kk][4 * ty + 2];
            float b0 = sB[kk][4 * tx + 0];
            float b1 = sB[kk][4 * tx + 1];
            float b2 = sB[kk][4 * tx + 2];
            float b3 = sB[kk][4 * tx + 3];
            unsigned long long d0 = pack2(b0, b0);
            unsigned long long d1 = pack2(b1, b1);
            unsigned long long d2 = pack2(b2, b2);
            unsigned long long d3 = pack2(b3, b3);
            fma2(acc[0][0], a0, d0); fma2(acc[1][0], a1, d0);
            fma2(acc[0][1], a0, d1); fma2(acc[1][1], a1, d1);
            fma2(acc[0][2], a0, d2); fma2(acc[1][2], a1, d2);
            fma2(acc[0][3], a0, d3); fma2(acc[1][3], a1, d3);
        }
        __syncthreads();
    }

    float bias[4];
#pragma unroll
    for (int c = 0; c < 4; ++c) {
        int n = n0 + 4 * tx + c;
        bias[c] = bih[n] + bhh[n];
    }
#pragma unroll
    for (int p = 0; p < 2; ++p) {
        float2 v0 = unpack2(acc[p][0]);
        float2 v1 = unpack2(acc[p][1]);
        float2 v2 = unpack2(acc[p][2]);
        float2 v3 = unpack2(acc[p][3]);
        int row0 = m0 + 4 * ty + 2 * p;
        float4 o0 = make_float4(v0.x + bias[0], v1.x + bias[1], v2.x + bias[2], v3.x + bias[3]);
        float4 o1 = make_float4(v0.y + bias[0], v1.y + bias[1], v2.y + bias[2], v3.y + bias[3]);
        *(float4*)&g_xproj[(size_t)row0 * G4n + n0 + 4 * tx]       = o0;
        *(float4*)&g_xproj[(size_t)(row0 + 1) * G4n + n0 + 4 * tx] = o1;
    }
}

// ============================================================================
// Kernel 2: one LSTM timestep.
//   gates[b, :] = x_proj[b, t, :] + h_{t-1}[b, :] @ W_hh^T   (M=64, N=4096, K=1024)
//   CTA: all 64 batch rows x 8 columns of EACH of the 4 gate chunks (i,f,g,o),
//   so the pointwise combine is thread-local. grid = 128 CTAs, 128 threads.
//   Thread: 4 batch rows (2 f32x2 pairs) x 1 col x 4 gates = 8 FFMA2 / kk.
// ============================================================================
__global__ __launch_bounds__(128) void step_kernel(
    const float* __restrict__ Whh,   // (4H, H)
    float* __restrict__ hs,          // (B, T, H)
    float* __restrict__ cs,          // (B, T, H)
    int t)
{
    __shared__ float sh[64][66];     // transposed h tile: sh[kk][batch], pad 66
    __shared__ float sw[64][33];     // transposed W tile: sw[kk][c], pad 33 -> conflict-free STS

    const int tid = threadIdx.x;
    const int tx  = tid & 7;         // column within the 8-col slice
    const int ty  = tid >> 3;        // 16 row groups (4 rows each)
    const int j0  = blockIdx.x * 8;  // column slice base within H

    unsigned long long acc[4][2];
#pragma unroll
    for (int q = 0; q < 4; ++q) { acc[q][0] = 0ULL; acc[q][1] = 0ULL; }

    for (int kt = 0; kt < 16; ++kt) {
        const int k0 = kt * 64;

        // ---- h fill: 1024 float4 items (r in [0,64), q in [0,16)) ----
        // lane mapping keeps global LDG coalesced (128B runs) and STS 2-way max.
#pragma unroll
        for (int nIt = 0; nIt < 8; ++nIt) {
            int i = tid + nIt * 128;
            int q = (i & 7) | ((i >> 6) & 8);   // qlo = bits[0:3), qhi = bit 9
            int r = (i >> 3) & 63;
            float4 v;
            if (t > 0)
                v = *(const float4*)&hs[((size_t)r * Tn + (t - 1)) * Hn + k0 + 4 * q];
            else
                v = make_float4(0.f, 0.f, 0.f, 0.f);
            sh[4 * q + 0][r] = v.x; sh[4 * q + 1][r] = v.y;
            sh[4 * q + 2][r] = v.z; sh[4 * q + 3][r] = v.w;
        }
        // ---- W fill: 512 float4 items (c in [0,32), q in [0,16)) ----
#pragma unroll
        for (int nIt = 0; nIt < 4; ++nIt) {
            int i = tid + nIt * 128;
            int q = (i & 7) | ((i >> 5) & 8);   // qlo = bits[0:3), qhi = bit 8
            int c = (i >> 3) & 31;
            int grow = (c >> 3) * Hn + j0 + (c & 7);   // gate*H + column
            float4 v = *(const float4*)&Whh[(size_t)grow * Hn + k0 + 4 * q];
            sw[4 * q + 0][c] = v.x; sw[4 * q + 1][c] = v.y;
            sw[4 * q + 2][c] = v.z; sw[4 * q + 3][c] = v.w;
        }
        __syncthreads();

#pragma unroll 16
        for (int kk = 0; kk < 64; ++kk) {
            unsigned long long h0 = *(const unsigned long long*)&sh[kk][4 * ty];
            unsigned long long h1 = *(const unsigned long long*)&sh[kk][4 * ty + 2];
#pragma unroll
            for (int qg = 0; qg < 4; ++qg) {
                float w = sw[kk][qg * 8 + tx];
                unsigned long long wd = pack2(w, w);
                fma2(acc[qg][0], h0, wd);
                fma2(acc[qg][1], h1, wd);
            }
        }
        __syncthreads();
    }

    // ---- pointwise LSTM epilogue ----
    const int j = j0 + tx;
#pragma unroll
    for (int p = 0; p < 2; ++p) {
        float2 gi = unpack2(acc[0][p]);
        float2 gf = unpack2(acc[1][p]);
        float2 gg = unpack2(acc[2][p]);
        float2 go = unpack2(acc[3][p]);
#pragma unroll
        for (int e = 0; e < 2; ++e) {
            int row = 4 * ty + 2 * p + e;
            size_t bt = (size_t)row * Tn + t;
            const float* xp = &g_xproj[bt * G4n];
            float ai = (e ? gi.y : gi.x) + xp[j];
            float af = (e ? gf.y : gf.x) + xp[Hn + j];
            float ag = (e ? gg.y : gg.x) + xp[2 * Hn + j];
            float ao = (e ? go.y : go.x) + xp[3 * Hn + j];
            float iv = sigf(ai);
            float fv = sigf(af);
            float gv = tanhf(ag);
            float ov = sigf(ao);
            float cp = (t > 0) ? cs[((size_t)row * Tn + t - 1) * Hn + j] : 0.f;
            float cn = fv * cp + iv * gv;
            float hn = ov * tanhf(cn);
            hs[bt * Hn + j] = hn;
            cs[bt * Hn + j] = cn;
        }
    }
}

// ============================================================================
// Kernel 3: gather h_last / c_last via length
// ============================================================================
__global__ void gather_kernel(const float* __restrict__ hs,
                              const float* __restrict__ cs,
                              const int* __restrict__ length,
                              float* __restrict__ h_last,
                              float* __restrict__ c_last)
{
    int b = blockIdx.x;
    int j = threadIdx.x;
    int t = length[b] - 1;
    size_t src = ((size_t)b * Tn + t) * Hn + j;
    size_t dst = (size_t)b * Hn + j;
    h_last[dst] = hs[src];
    c_last[dst] = cs[src];
}

// ============================================================================
extern "C" void kernel_launch(void* const* d_in, const int* in_sizes, int n_in,
                              void* d_out, int out_size)
{
    (void)in_sizes; (void)n_in; (void)out_size;
    const float* inputs = (const float*)d_in[0];   // (B, T, DI)
    const float* W_ih   = (const float*)d_in[1];   // (4H, DI)
    const float* W_hh   = (const float*)d_in[2];   // (4H, H)
    const float* b_ih   = (const float*)d_in[3];   // (4H,)
    const float* b_hh   = (const float*)d_in[4];   // (4H,)
    const int*   length = (const int*)d_in[5];     // (B,)

    float* out    = (float*)d_out;
    float* hs     = out;                                   // (B, T, H)
    float* cs     = hs + (size_t)Bn * Tn * Hn;             // (B, T, H)
    float* h_last = cs + (size_t)Bn * Tn * Hn;             // (B, H)
    float* c_last = h_last + (size_t)Bn * Hn;              // (B, H)

    // 1) x_proj = inputs @ W_ih^T + (b_ih + b_hh)
    dim3 g1(G4n / 64, (Bn * Tn) / 64);
    xproj_kernel<<<g1, 256>>>(inputs, W_ih, b_ih, b_hh);

    // 2) sequential recurrence, one launch per timestep
    for (int t = 0; t < Tn; ++t)
        step_kernel<<<128, 128>>>(W_hh, hs, cs, t);

    // 3) gather last valid states
    gather_kernel<<<Bn, Hn>>>(hs, cs, length, h_last, c_last);
}

// round 3
// speedup vs baseline: 1.2356x; 1.2356x over previous
#include <cuda_runtime.h>
#include <cstdint>
#include <cstddef>

#define Bn  64
#define Tn  512
#define DIn 512
#define Hn  1024
#define G4n 4096

// Scratch for the precomputed input projection: (B, T, 4H) fp32 = 512 MB.
__device__ float g_xproj[(size_t)Bn * Tn * G4n];
// Monotonic grid-barrier counter (never reset; base recovered by floor-div).
__device__ unsigned long long g_bar;

// ---------------- packed f32x2 helpers (exact fp32, 2x FFMA throughput) ----
__device__ __forceinline__ unsigned long long pack2(float lo, float hi) {
    unsigned long long r;
    asm("mov.b64 %0, {%1, %2};" : "=l"(r) : "f"(lo), "f"(hi));
    return r;
}
__device__ __forceinline__ void fma2(unsigned long long& d, unsigned long long a,
                                     unsigned long long b) {
    asm("fma.rn.f32x2 %0, %1, %2, %0;" : "+l"(d) : "l"(a), "l"(b));
}
__device__ __forceinline__ float2 unpack2(unsigned long long v) {
    float lo, hi;
    asm("mov.b64 {%0, %1}, %2;" : "=f"(lo), "=f"(hi) : "l"(v));
    return make_float2(lo, hi);
}

__device__ __forceinline__ float sigf(float x) {
    return 1.0f / (1.0f + __expf(-x));
}

// ============================================================================
// Kernel 1: x_proj = inputs @ W_ih^T + (b_ih + b_hh)   (unchanged, passing)
// ============================================================================
__global__ __launch_bounds__(256) void xproj_kernel(
    const float* __restrict__ A,      // (M, K) = inputs flattened
    const float* __restrict__ Wih,    // (N, K)
    const float* __restrict__ bih,
    const float* __restrict__ bhh)
{
    __shared__ float sA[32][66];
    __shared__ float sB[32][66];

    const int tid = threadIdx.x;
    const int tx  = tid & 15;
    const int ty  = tid >> 4;
    const int n0  = blockIdx.x * 64;
    const int m0  = blockIdx.y * 64;

    unsigned long long acc[2][4];
#pragma unroll
    for (int p = 0; p < 2; ++p)
#pragma unroll
        for (int c = 0; c < 4; ++c) acc[p][c] = 0ULL;

    for (int k0 = 0; k0 < DIn; k0 += 32) {
#pragma unroll
        for (int nIt = 0; nIt < 2; ++nIt) {
            int i = tid + nIt * 256;
            int q = i & 7;
            int r = i >> 3;
            float4 va = *(const float4*)&A[(size_t)(m0 + r) * DIn + k0 + 4 * q];
            sA[4 * q + 0][r] = va.x; sA[4 * q + 1][r] = va.y;
            sA[4 * q + 2][r] = va.z; sA[4 * q + 3][r] = va.w;
            float4 vb = *(const float4*)&Wih[(size_t)(n0 + r) * DIn + k0 + 4 * q];
            sB[4 * q + 0][r] = vb.x; sB[4 * q + 1][r] = vb.y;
            sB[4 * q + 2][r] = vb.z; sB[4 * q + 3][r] = vb.w;
        }
        __syncthreads();

#pragma unroll
        for (int kk = 0; kk < 32; ++kk) {
            unsigned long long a0 = *(const unsigned long long*)&sA[kk][4 * ty];
            unsigned long long a1 = *(const unsigned long long*)&sA[kk][4 * ty + 2];
            float b0 = sB[kk][4 * tx + 0];
            float b1 = sB[kk][4 * tx + 1];
            float b2 = sB[kk][4 * tx + 2];
            float b3 = sB[kk][4 * tx + 3];
            unsigned long long d0 = pack2(b0, b0);
            unsigned long long d1 = pack2(b1, b1);
            unsigned long long d2 = pack2(b2, b2);
            unsigned long long d3 = pack2(b3, b3);
            fma2(acc[0][0], a0, d0); fma2(acc[1][0], a1, d0);
            fma2(acc[0][1], a0, d1); fma2(acc[1][1], a1, d1);
            fma2(acc[0][2], a0, d2); fma2(acc[1][2], a1, d2);
            fma2(acc[0][3], a0, d3); fma2(acc[1][3], a1, d3);
        }
        __syncthreads();
    }

    float bias[4];
#pragma unroll
    for (int c = 0; c < 4; ++c) {
        int n = n0 + 4 * tx + c;
        bias[c] = bih[n] + bhh[n];
    }
#pragma unroll
    for (int p = 0; p < 2; ++p) {
        float2 v0 = unpack2(acc[p][0]);
        float2 v1 = unpack2(acc[p][1]);
        float2 v2 = unpack2(acc[p][2]);
        float2 v3 = unpack2(acc[p][3]);
        int row0 = m0 + 4 * ty + 2 * p;
        float4 o0 = make_float4(v0.x + bias[0], v1.x + bias[1], v2.x + bias[2], v3.x + bias[3]);
        float4 o1 = make_float4(v0.y + bias[0], v1.y + bias[1], v2.y + bias[2], v3.y + bias[3]);
        *(float4*)&g_xproj[(size_t)row0 * G4n + n0 + 4 * tx]       = o0;
        *(float4*)&g_xproj[(size_t)(row0 + 1) * G4n + n0 + 4 * tx] = o1;
    }
}

// ============================================================================
// Persistent recurrence kernel.
//   128 CTAs (1/SM, co-resident) x 256 threads. Each CTA owns 32 gate-columns
//   (8 per gate) and keeps its W_hh slice in SMEM for all 512 timesteps.
//   Per step: stream h_{t-1} in 8 cp.async double-buffered chunks, GEMM with
//   f32x2 FFMA, stage accs in SMEM, thread-local gate combine, grid barrier.
// ============================================================================
#define NCTA    128
#define NTHR    256
#define SW_PAD  34          // W tile row pad (even -> LDS.64 aligned; conflict-free STS)
#define SH_PAD  132         // h tile row pad (16B-aligned rows for cp.async)
#define SG_PAD  34
#define CHUNK   128
#define NCHUNK  (Hn / CHUNK)
#define BARS_PER_LAUNCH 511ULL

#define SW_FLOATS (Hn * SW_PAD)            // 34816
#define SH_FLOATS (2 * Bn * SH_PAD)        // 16896
#define SG_FLOATS (Bn * SG_PAD)            // 2176
#define SMEM_BYTES ((SW_FLOATS + SH_FLOATS + SG_FLOATS) * 4)   // 215552

__device__ __forceinline__ void cp_async16(uint32_t dst, const void* src) {
    asm volatile("cp.async.cg.shared.global [%0], [%1], 16;\n" :: "r"(dst), "l"(src));
}
__device__ __forceinline__ void cp_commit() {
    asm volatile("cp.async.commit_group;\n");
}
template <int N>
__device__ __forceinline__ void cp_wait() {
    asm volatile("cp.async.wait_group %0;\n" :: "n"(N));
}

__device__ __forceinline__ void load_h_chunk(uint32_t sh_addr, const float* __restrict__ hs,
                                             int tprev, int kt, int buf, int tid) {
    const int k0 = kt * CHUNK;
#pragma unroll
    for (int it = 0; it < 8; ++it) {
        int i  = tid + it * NTHR;
        int kc = i & 31;             // 16B chunk within the 128-float k range
        int r  = i >> 5;             // batch row 0..63
        const float* src = &hs[((size_t)r * Tn + tprev) * Hn + k0 + 4 * kc];
        uint32_t dst = sh_addr + (uint32_t)(((buf * Bn + r) * SH_PAD + 4 * kc) * 4);
        cp_async16(dst, src);
    }
}

__global__ __launch_bounds__(NTHR, 1) void lstm_persistent(
    const float* __restrict__ Whh,   // (4H, H)
    float* __restrict__ hs,          // (B, T, H)
    float* __restrict__ cs)          // (B, T, H)
{
    extern __shared__ float smem[];
    float* sw = smem;                          // [Hn][SW_PAD]  W slice (k-major)
    float* sh = sw + SW_FLOATS;                // [2][Bn][SH_PAD] h chunk double buffer
    float* sg = sh + SH_FLOATS;                // [Bn][SG_PAD]  staged gate partials

    const int tid = threadIdx.x;
    const int g   = tid & 7;       // 4-col group within the 32-col slice
    const int rg  = tid >> 3;      // 2-row group, 0..31
    const int j0  = blockIdx.x * 8;

    // ---- load W slice (32 cols x 1024 k) into SMEM, k-major, once ----
#pragma unroll 4
    for (int it = 0; it < 32; ++it) {
        int i  = tid + it * NTHR;
        int c  = i & 31;                 // c = gate*8 + jj
        int kq = i >> 5;                 // float4 index along k, 0..255
        int gate = c >> 3, jj = c & 7;
        const float4 v = *(const float4*)&Whh[(size_t)(gate * Hn + j0 + jj) * Hn + 4 * kq];
        sw[(4 * kq + 0) * SW_PAD + c] = v.x;
        sw[(4 * kq + 1) * SW_PAD + c] = v.y;
        sw[(4 * kq + 2) * SW_PAD + c] = v.z;
        sw[(4 * kq + 3) * SW_PAD + c] = v.w;
    }

    // ---- recover barrier base (robust across graph replays) ----
    unsigned long long base = 0;
    if (tid == 0) {
        unsigned long long v = atomicAdd(&g_bar, 0ULL);
        base = (v / (BARS_PER_LAUNCH * NCTA)) * (BARS_PER_LAUNCH * NCTA);
    }
    __syncthreads();

    const uint32_t sh_addr = (uint32_t)__cvta_generic_to_shared(sh);

    for (int t = 0; t < Tn; ++t) {
        // ---- prefetch x_proj + c_prev for this thread's 2 epilogue cells ----
        float xpv[2][4], cpv[2];
#pragma unroll
        for (int it = 0; it < 2; ++it) {
            int cell = tid + it * NTHR;      // 0..511
            int b  = cell >> 3;
            int jj = cell & 7;
            int j  = j0 + jj;
            const float* xp = &g_xproj[((size_t)b * Tn + t) * G4n + j];
            xpv[it][0] = xp[0];
            xpv[it][1] = xp[Hn];
            xpv[it][2] = xp[2 * Hn];
            xpv[it][3] = xp[3 * Hn];
            cpv[it] = (t > 0) ? cs[((size_t)b * Tn + t - 1) * Hn + j] : 0.0f;
        }

        unsigned long long a00 = 0, a01 = 0, a10 = 0, a11 = 0;

        if (t > 0) {
            load_h_chunk(sh_addr, hs, t - 1, 0, 0, tid);
            cp_commit();
#pragma unroll 1
            for (int kt = 0; kt < NCHUNK; ++kt) {
                if (kt + 1 < NCHUNK) {
                    load_h_chunk(sh_addr, hs, t - 1, kt + 1, (kt + 1) & 1, tid);
                    cp_commit();
                    cp_wait<1>();
                } else {
                    cp_wait<0>();
                }
                __syncthreads();

                const float* hb = sh + ((kt & 1) * Bn + 2 * rg) * SH_PAD;
                const float* wb = sw + (size_t)(kt * CHUNK) * SW_PAD + 4 * g;
#pragma unroll 16
                for (int kk = 0; kk < CHUNK; ++kk) {
                    float h0 = hb[kk];
                    float h1 = hb[SH_PAD + kk];
                    unsigned long long H0 = pack2(h0, h0);
                    unsigned long long H1 = pack2(h1, h1);
                    unsigned long long w01 = *(const unsigned long long*)&wb[kk * SW_PAD];
                    unsigned long long w23 = *(const unsigned long long*)&wb[kk * SW_PAD + 2];
                    fma2(a00, H0, w01); fma2(a01, H0, w23);
                    fma2(a10, H1, w01); fma2(a11, H1, w23);
                }
                __syncthreads();
            }
        }

        // ---- stage gate partials to SMEM (cols-packed -> scalar layout) ----
        {
            int r0 = 2 * rg;
            *(unsigned long long*)&sg[r0 * SG_PAD + 4 * g]           = a00;
            *(unsigned long long*)&sg[r0 * SG_PAD + 4 * g + 2]       = a01;
            *(unsigned long long*)&sg[(r0 + 1) * SG_PAD + 4 * g]     = a10;
            *(unsigned long long*)&sg[(r0 + 1) * SG_PAD + 4 * g + 2] = a11;
        }
        __syncthreads();

        // ---- thread-local LSTM gate combine: 2 cells per thread ----
#pragma unroll
        for (int it = 0; it < 2; ++it) {
            int cell = tid + it * NTHR;
            int b  = cell >> 3;
            int jj = cell & 7;
            int j  = j0 + jj;
            float gi = sg[b * SG_PAD + jj]      + xpv[it][0];
            float gf = sg[b * SG_PAD + 8 + jj]  + xpv[it][1];
            float gg = sg[b * SG_PAD + 16 + jj] + xpv[it][2];
            float go = sg[b * SG_PAD + 24 + jj] + xpv[it][3];
            float iv = sigf(gi);
            float fv = sigf(gf);
            float gv = tanhf(gg);
            float ov = sigf(go);
            float cn = fv * cpv[it] + iv * gv;
            float hn = ov * tanhf(cn);
            size_t o = ((size_t)b * Tn + t) * Hn + j;
            hs[o] = hn;
            cs[o] = cn;
        }
        __syncthreads();   // protect sg / allow safe reuse

        // ---- grid barrier between steps (skip after the last one) ----
        if (t < Tn - 1) {
            __threadfence();
            __syncthreads();
            if (tid == 0) {
                atomicAdd(&g_bar, 1ULL);
                unsigned long long target = base + (unsigned long long)(t + 1) * NCTA;
                unsigned long long v;
                do {
                    asm volatile("ld.acquire.gpu.global.u64 %0, [%1];"
                                 : "=l"(v) : "l"(&g_bar) : "memory");
                    if (v < target) __nanosleep(32);
                } while (v < target);
            }
            __syncthreads();
        }
    }
}

// ============================================================================
// Kernel 3: gather h_last / c_last via length
// ============================================================================
__global__ void gather_kernel(const float* __restrict__ hs,
                              const float* __restrict__ cs,
                              const int* __restrict__ length,
                              float* __restrict__ h_last,
                              float* __restrict__ c_last)
{
    int b = blockIdx.x;
    int j = threadIdx.x;
    int t = length[b] - 1;
    size_t src = ((size_t)b * Tn + t) * Hn + j;
    size_t dst = (size_t)b * Hn + j;
    h_last[dst] = hs[src];
    c_last[dst] = cs[src];
}

// ============================================================================
extern "C" void kernel_launch(void* const* d_in, const int* in_sizes, int n_in,
                              void* d_out, int out_size)
{
    (void)in_sizes; (void)n_in; (void)out_size;
    const float* inputs = (const float*)d_in[0];   // (B, T, DI)
    const float* W_ih   = (const float*)d_in[1];   // (4H, DI)
    const float* W_hh   = (const float*)d_in[2];   // (4H, H)
    const float* b_ih   = (const float*)d_in[3];   // (4H,)
    const float* b_hh   = (const float*)d_in[4];   // (4H,)
    const int*   length = (const int*)d_in[5];     // (B,)

    float* out    = (float*)d_out;
    float* hs     = out;                                   // (B, T, H)
    float* cs     = hs + (size_t)Bn * Tn * Hn;             // (B, T, H)
    float* h_last = cs + (size_t)Bn * Tn * Hn;             // (B, H)
    float* c_last = h_last + (size_t)Bn * Hn;              // (B, H)

    // 1) x_proj = inputs @ W_ih^T + (b_ih + b_hh)
    dim3 g1(G4n / 64, (Bn * Tn) / 64);
    xproj_kernel<<<g1, 256>>>(inputs, W_ih, b_ih, b_hh);

    // 2) persistent recurrence (single launch, grid-wide software barrier)
    static bool attr_set = false;
    if (!attr_set) {
        cudaFuncSetAttribute(lstm_persistent,
                             cudaFuncAttributeMaxDynamicSharedMemorySize, SMEM_BYTES);
        attr_set = true;
    }
    lstm_persistent<<<NCTA, NTHR, SMEM_BYTES>>>(W_hh, hs, cs);

    // 3) gather last valid states
    gather_kernel<<<Bn, Hn>>>(hs, cs, length, h_last, c_last);
}

// round 4
// speedup vs baseline: 1.2371x; 1.0012x over previous
#include <cuda_runtime.h>
#include <cstdint>
#include <cstddef>

#define Bn  64
#define Tn  512
#define DIn 512
#define Hn  1024
#define G4n 4096

typedef unsigned long long ull;

// Scratch for the precomputed input projection: (B, T, 4H) fp32 = 512 MB.
__device__ float g_xproj[(size_t)Bn * Tn * G4n];

#define NCTA    128
// Per-CTA monotonic step flags for the distributed grid barrier.
__device__ ull g_flags[NCTA];

// ---------------- packed f32x2 helpers (exact fp32, 2x FFMA throughput) ----
__device__ __forceinline__ ull pack2(float lo, float hi) {
    ull r;
    asm("mov.b64 %0, {%1, %2};" : "=l"(r) : "f"(lo), "f"(hi));
    return r;
}
__device__ __forceinline__ void fma2(ull& d, ull a, ull b) {
    asm("fma.rn.f32x2 %0, %1, %2, %0;" : "+l"(d) : "l"(a), "l"(b));
}
__device__ __forceinline__ ull add2(ull a, ull b) {
    ull r;
    asm("add.rn.f32x2 %0, %1, %2;" : "=l"(r) : "l"(a), "l"(b));
    return r;
}
__device__ __forceinline__ float2 unpack2(ull v) {
    float lo, hi;
    asm("mov.b64 {%0, %1}, %2;" : "=f"(lo), "=f"(hi) : "l"(v));
    return make_float2(lo, hi);
}

__device__ __forceinline__ float sigf(float x) {
    return 1.0f / (1.0f + __expf(-x));
}

// ============================================================================
// Kernel 1: x_proj = inputs @ W_ih^T + (b_ih + b_hh)
//   M = 32768, N = 4096, K = 512.  Tile 128x128x32, 256 threads, 8x8/thread.
//   Lanes pack column pairs (f32x2); A broadcast via LDS.128, B via 4
//   conflict-free LDS.64 (cols = 2*tx + 32*cp covers all 32 banks).
//   FFMA2 issue density ~70% (vs 40% in the old 64x64 kernel, which was
//   L1-bound at 97%).
// ============================================================================
#define XK 32
__global__ __launch_bounds__(256, 2) void xproj_kernel(
    const float* __restrict__ A,      // (M, K)
    const float* __restrict__ Wih,    // (N, K)
    const float* __restrict__ bih,
    const float* __restrict__ bhh)
{
    __shared__ float sA[XK][132];   // transposed: sA[kk][m-row]
    __shared__ float sB[XK][132];   // transposed: sB[kk][n-col]

    const int tid = threadIdx.x;
    const int tx  = tid & 15;       // 16 col groups
    const int ty  = tid >> 4;       // 16 row groups (8 rows each)
    const int n0  = blockIdx.x * 128;
    const int m0  = blockIdx.y * 128;

    ull acc[8][4];
#pragma unroll
    for (int r = 0; r < 8; ++r)
#pragma unroll
        for (int c = 0; c < 4; ++c) acc[r][c] = 0ULL;

    for (int k0 = 0; k0 < DIn; k0 += XK) {
        // Fill: 1024 float4 per matrix; q-fast lanes -> coalesced-ish LDG.128.
#pragma unroll
        for (int it = 0; it < 4; ++it) {
            int i = tid + it * 256;
            int q = i & 7;            // float4 index within the 32-k row
            int r = i >> 3;           // 0..127
            float4 va = *(const float4*)&A[(size_t)(m0 + r) * DIn + k0 + 4 * q];
            sA[4 * q + 0][r] = va.x; sA[4 * q + 1][r] = va.y;
            sA[4 * q + 2][r] = va.z; sA[4 * q + 3][r] = va.w;
            float4 vb = *(const float4*)&Wih[(size_t)(n0 + r) * DIn + k0 + 4 * q];
            sB[4 * q + 0][r] = vb.x; sB[4 * q + 1][r] = vb.y;
            sB[4 * q + 2][r] = vb.z; sB[4 * q + 3][r] = vb.w;
        }
        __syncthreads();

#pragma unroll
        for (int kk = 0; kk < XK; ++kk) {
            float4 a0 = *(const float4*)&sA[kk][8 * ty];
            float4 a1 = *(const float4*)&sA[kk][8 * ty + 4];
            ull b0 = *(const ull*)&sB[kk][2 * tx];
            ull b1 = *(const ull*)&sB[kk][2 * tx + 32];
            ull b2 = *(const ull*)&sB[kk][2 * tx + 64];
            ull b3 = *(const ull*)&sB[kk][2 * tx + 96];
            ull A0 = pack2(a0.x, a0.x), A1 = pack2(a0.y, a0.y);
            ull A2 = pack2(a0.z, a0.z), A3 = pack2(a0.w, a0.w);
            ull A4 = pack2(a1.x, a1.x), A5 = pack2(a1.y, a1.y);
            ull A6 = pack2(a1.z, a1.z), A7 = pack2(a1.w, a1.w);
            fma2(acc[0][0], A0, b0); fma2(acc[0][1], A0, b1);
            fma2(acc[0][2], A0, b2); fma2(acc[0][3], A0, b3);
            fma2(acc[1][0], A1, b0); fma2(acc[1][1], A1, b1);
            fma2(acc[1][2], A1, b2); fma2(acc[1][3], A1, b3);
            fma2(acc[2][0], A2, b0); fma2(acc[2][1], A2, b1);
            fma2(acc[2][2], A2, b2); fma2(acc[2][3], A2, b3);
            fma2(acc[3][0], A3, b0); fma2(acc[3][1], A3, b1);
            fma2(acc[3][2], A3, b2); fma2(acc[3][3], A3, b3);
            fma2(acc[4][0], A4, b0); fma2(acc[4][1], A4, b1);
            fma2(acc[4][2], A4, b2); fma2(acc[4][3], A4, b3);
            fma2(acc[5][0], A5, b0); fma2(acc[5][1], A5, b1);
            fma2(acc[5][2], A5, b2); fma2(acc[5][3], A5, b3);
            fma2(acc[6][0], A6, b0); fma2(acc[6][1], A6, b1);
            fma2(acc[6][2], A6, b2); fma2(acc[6][3], A6, b3);
            fma2(acc[7][0], A7, b0); fma2(acc[7][1], A7, b1);
            fma2(acc[7][2], A7, b2); fma2(acc[7][3], A7, b3);
        }
        __syncthreads();
    }

    // bias pairs per colpair, then packed add + 8B stores (coalesced 128B/warp)
    ull bp[4];
#pragma unroll
    for (int cp = 0; cp < 4; ++cp) {
        int c0 = n0 + 32 * cp + 2 * tx;
        bp[cp] = pack2(bih[c0] + bhh[c0], bih[c0 + 1] + bhh[c0 + 1]);
    }
#pragma unroll
    for (int r = 0; r < 8; ++r) {
        int row = m0 + 8 * ty + r;
#pragma unroll
        for (int cp = 0; cp < 4; ++cp) {
            ull d = add2(acc[r][cp], bp[cp]);
            *(ull*)&g_xproj[(size_t)row * G4n + n0 + 32 * cp + 2 * tx] = d;
        }
    }
}

// ============================================================================
// Persistent recurrence kernel (128 CTAs x 256 thr, W_hh pinned in SMEM).
//   Changes this round: distributed per-CTA flag barrier (release store +
//   per-thread acquire polls), c-state held in registers across all steps.
// ============================================================================
#define NTHR    256
#define SW_PAD  34
#define SH_PAD  132
#define SG_PAD  34
#define CHUNK   128
#define NCHUNK  (Hn / CHUNK)

#define SW_FLOATS (Hn * SW_PAD)
#define SH_FLOATS (2 * Bn * SH_PAD)
#define SG_FLOATS (Bn * SG_PAD)
#define SMEM_BYTES ((SW_FLOATS + SH_FLOATS + SG_FLOATS) * 4 + 16)

__device__ __forceinline__ void cp_async16(uint32_t dst, const void* src) {
    asm volatile("cp.async.cg.shared.global [%0], [%1], 16;\n" :: "r"(dst), "l"(src));
}
__device__ __forceinline__ void cp_commit() {
    asm volatile("cp.async.commit_group;\n");
}
template <int N>
__device__ __forceinline__ void cp_wait() {
    asm volatile("cp.async.wait_group %0;\n" :: "n"(N));
}

__device__ __forceinline__ void load_h_chunk(uint32_t sh_addr, const float* __restrict__ hs,
                                             int tprev, int kt, int buf, int tid) {
    const int k0 = kt * CHUNK;
#pragma unroll
    for (int it = 0; it < 8; ++it) {
        int i  = tid + it * NTHR;
        int kc = i & 31;
        int r  = i >> 5;
        const float* src = &hs[((size_t)r * Tn + tprev) * Hn + k0 + 4 * kc];
        uint32_t dst = sh_addr + (uint32_t)(((buf * Bn + r) * SH_PAD + 4 * kc) * 4);
        cp_async16(dst, src);
    }
}

__global__ __launch_bounds__(NTHR, 1) void lstm_persistent(
    const float* __restrict__ Whh,   // (4H, H)
    float* __restrict__ hs,          // (B, T, H)
    float* __restrict__ cs)          // (B, T, H)
{
    extern __shared__ float smem[];
    float* sw = smem;                          // [Hn][SW_PAD]  W slice (k-major)
    float* sh = sw + SW_FLOATS;                // [2][Bn][SH_PAD] h double buffer
    float* sg = sh + SH_FLOATS;                // [Bn][SG_PAD]  staged gate partials
    ull* s_base = (ull*)(sg + SG_FLOATS);

    const int tid = threadIdx.x;
    const int g   = tid & 7;       // 4-col group within the 32-col slice
    const int rg  = tid >> 3;      // 2-row group, 0..31
    const int j0  = blockIdx.x * 8;

    // ---- load W slice (32 cols x 1024 k) into SMEM, k-major, once ----
#pragma unroll 4
    for (int it = 0; it < 32; ++it) {
        int i  = tid + it * NTHR;
        int c  = i & 31;                 // c = gate*8 + jj
        int kq = i >> 5;                 // float4 index along k
        int gate = c >> 3, jj = c & 7;
        const float4 v = *(const float4*)&Whh[(size_t)(gate * Hn + j0 + jj) * Hn + 4 * kq];
        sw[(4 * kq + 0) * SW_PAD + c] = v.x;
        sw[(4 * kq + 1) * SW_PAD + c] = v.y;
        sw[(4 * kq + 2) * SW_PAD + c] = v.z;
        sw[(4 * kq + 3) * SW_PAD + c] = v.w;
    }

    // ---- recover barrier base (monotonic flags; equal across CTAs at start)
    if (tid == 0) *s_base = g_flags[blockIdx.x];
    __syncthreads();
    const ull base = *s_base;

    const uint32_t sh_addr = (uint32_t)__cvta_generic_to_shared(sh);

    // c state lives in registers: each thread owns 2 fixed (b, j) cells.
    float creg[2] = {0.0f, 0.0f};

    for (int t = 0; t < Tn; ++t) {
        // ---- kick off first h chunk ASAP ----
        if (t > 0) {
            load_h_chunk(sh_addr, hs, t - 1, 0, 0, tid);
            cp_commit();
        }

        // ---- prefetch x_proj for this thread's 2 epilogue cells ----
        float xpv[2][4];
#pragma unroll
        for (int it = 0; it < 2; ++it) {
            int cell = tid + it * NTHR;
            int b  = cell >> 3;
            int jj = cell & 7;
            const float* xp = &g_xproj[((size_t)b * Tn + t) * G4n + j0 + jj];
            xpv[it][0] = xp[0];
            xpv[it][1] = xp[Hn];
            xpv[it][2] = xp[2 * Hn];
            xpv[it][3] = xp[3 * Hn];
        }

        ull a00 = 0, a01 = 0, a10 = 0, a11 = 0;

        if (t > 0) {
#pragma unroll 1
            for (int kt = 0; kt < NCHUNK; ++kt) {
                if (kt + 1 < NCHUNK) {
                    load_h_chunk(sh_addr, hs, t - 1, kt + 1, (kt + 1) & 1, tid);
                    cp_commit();
                    cp_wait<1>();
                } else {
                    cp_wait<0>();
                }
                __syncthreads();

                const float* hb = sh + ((kt & 1) * Bn + 2 * rg) * SH_PAD;
                const float* wb = sw + (size_t)(kt * CHUNK) * SW_PAD + 4 * g;
#pragma unroll 16
                for (int kk = 0; kk < CHUNK; ++kk) {
                    float h0 = hb[kk];
                    float h1 = hb[SH_PAD + kk];
                    ull H0 = pack2(h0, h0);
                    ull H1 = pack2(h1, h1);
                    ull w01 = *(const ull*)&wb[kk * SW_PAD];
                    ull w23 = *(const ull*)&wb[kk * SW_PAD + 2];
                    fma2(a00, H0, w01); fma2(a01, H0, w23);
                    fma2(a10, H1, w01); fma2(a11, H1, w23);
                }
                __syncthreads();
            }
        }

        // ---- stage gate partials to SMEM ----
        {
            int r0 = 2 * rg;
            *(ull*)&sg[r0 * SG_PAD + 4 * g]           = a00;
            *(ull*)&sg[r0 * SG_PAD + 4 * g + 2]       = a01;
            *(ull*)&sg[(r0 + 1) * SG_PAD + 4 * g]     = a10;
            *(ull*)&sg[(r0 + 1) * SG_PAD + 4 * g + 2] = a11;
        }
        __syncthreads();

        // ---- thread-local LSTM gate combine: 2 cells per thread ----
#pragma unroll
        for (int it = 0; it < 2; ++it) {
            int cell = tid + it * NTHR;
            int b  = cell >> 3;
            int jj = cell & 7;
            int j  = j0 + jj;
            float gi = sg[b * SG_PAD + jj]      + xpv[it][0];
            float gf = sg[b * SG_PAD + 8 + jj]  + xpv[it][1];
            float gg = sg[b * SG_PAD + 16 + jj] + xpv[it][2];
            float go = sg[b * SG_PAD + 24 + jj] + xpv[it][3];
            float iv = sigf(gi);
            float fv = sigf(gf);
            float gv = tanhf(gg);
            float ov = sigf(go);
            float cn = fv * creg[it] + iv * gv;
            float hn = ov * tanhf(cn);
            creg[it] = cn;
            size_t o = ((size_t)b * Tn + t) * Hn + j;
            hs[o] = hn;
            cs[o] = cn;
        }

        // ---- distributed grid barrier between steps ----
        if (t < Tn - 1) {
            __syncthreads();                       // all hs/cs stores issued
            if (tid == 0) {
                asm volatile("st.release.gpu.global.u64 [%0], %1;"
                             :: "l"(&g_flags[blockIdx.x]),
                                "l"(base + (ull)(t + 1)) : "memory");
            }
            if (tid < NCTA) {
                const ull target = base + (ull)(t + 1);
                ull v;
                do {
                    asm volatile("ld.acquire.gpu.global.u64 %0, [%1];"
                                 : "=l"(v) : "l"(&g_flags[tid]) : "memory");
                    if (v < target) __nanosleep(20);
                } while (v < target);
            }
            __syncthreads();
        } else {
            __syncthreads();                       // protect sg before next reuse
        }
    }
}

// ============================================================================
// Kernel 3: gather h_last / c_last via length
// ============================================================================
__global__ void gather_kernel(const float* __restrict__ hs,
                              const float* __restrict__ cs,
                              const int* __restrict__ length,
                              float* __restrict__ h_last,
                              float* __restrict__ c_last)
{
    int b = blockIdx.x;
    int j = threadIdx.x;
    int t = length[b] - 1;
    size_t src = ((size_t)b * Tn + t) * Hn + j;
    size_t dst = (size_t)b * Hn + j;
    h_last[dst] = hs[src];
    c_last[dst] = cs[src];
}

// ============================================================================
extern "C" void kernel_launch(void* const* d_in, const int* in_sizes, int n_in,
                              void* d_out, int out_size)
{
    (void)in_sizes; (void)n_in; (void)out_size;
    const float* inputs = (const float*)d_in[0];   // (B, T, DI)
    const float* W_ih   = (const float*)d_in[1];   // (4H, DI)
    const float* W_hh   = (const float*)d_in[2];   // (4H, H)
    const float* b_ih   = (const float*)d_in[3];   // (4H,)
    const float* b_hh   = (const float*)d_in[4];   // (4H,)
    const int*   length = (const int*)d_in[5];     // (B,)

    float* out    = (float*)d_out;
    float* hs     = out;                                   // (B, T, H)
    float* cs     = hs + (size_t)Bn * Tn * Hn;             // (B, T, H)
    float* h_last = cs + (size_t)Bn * Tn * Hn;             // (B, H)
    float* c_last = h_last + (size_t)Bn * Hn;              // (B, H)

    // 1) x_proj = inputs @ W_ih^T + (b_ih + b_hh)
    dim3 g1(G4n / 128, (Bn * Tn) / 128);
    xproj_kernel<<<g1, 256>>>(inputs, W_ih, b_ih, b_hh);

    // 2) persistent recurrence (single launch, distributed flag barrier)
    static bool attr_set = false;
    if (!attr_set) {
        cudaFuncSetAttribute(lstm_persistent,
                             cudaFuncAttributeMaxDynamicSharedMemorySize, SMEM_BYTES);
        attr_set = true;
    }
    lstm_persistent<<<NCTA, NTHR, SMEM_BYTES>>>(W_hh, hs, cs);

    // 3) gather last valid states
    gather_kernel<<<Bn, Hn>>>(hs, cs, length, h_last, c_last);
}